// round 14
// baseline (speedup 1.0000x reference)
#include <cuda_runtime.h>
#include <cuda_bf16.h>
#include <mma.h>

using namespace nvcuda;

// EdgeNetwork:
//   P[node] = [h@W1_top | h@W1_mid]  (100000 x 384 fp32, precomputed, WMMA bf16x3)
//   out[e]  = tanh(relu(P[dst,0:192]+P[src,192:384]+dR*W1[256,:]+b1) @ W2 + b2)
// Edge phase: persistent MERGED kernel — every warp gathers (reg-resident,
// coalesced 8-lane groups) AND does MMA; next tile's LDGs issued before MMA
// so gather latency hides behind tensor work. Single A buffer, 2 syncs/tile.

#define N_NODES 100000
#define E_TOTAL 640000
#define NTILES  (E_TOTAL / 64)     // 10000
#define GRID_P  148

__device__ float gP[(size_t)N_NODES * 384];
__device__ __align__(16) unsigned short gW1h[256 * 192];  // [k][n] bf16 hi
__device__ __align__(16) unsigned short gW1l[256 * 192];
__device__ __align__(16) unsigned short gW2h[192 * 128];  // [k][n]
__device__ __align__(16) unsigned short gW2l[192 * 128];

__device__ __forceinline__ void split_bf(float v, unsigned short& hi, unsigned short& lo) {
    __nv_bfloat16 bh = __float2bfloat16(v);
    __nv_bfloat16 bl = __float2bfloat16(v - __bfloat162float(bh));
    hi = __bfloat16_as_ushort(bh);
    lo = __bfloat16_as_ushort(bl);
}
__device__ __forceinline__ unsigned pack2(unsigned short a, unsigned short b) {
    return (unsigned)a | ((unsigned)b << 16);
}
__device__ __forceinline__ unsigned cvt_bf16x2(float hi_val, float lo_val) {
    unsigned r;
    asm("cvt.rn.bf16x2.f32 %0, %1, %2;" : "=r"(r) : "f"(hi_val), "f"(lo_val));
    return r;
}
__device__ __forceinline__ float bf_lo_f32(unsigned p) {
    return __uint_as_float(p << 16);
}
__device__ __forceinline__ float bf_hi_f32(unsigned p) {
    return __uint_as_float(p & 0xffff0000u);
}
__device__ __forceinline__ float fast_tanh(float x) {
    float z = __expf(-2.0f * fabsf(x));
    float r = (1.0f - z) * __fdividef(1.0f, 1.0f + z);
    return copysignf(r, x);
}

__global__ void convert_weights(const float* __restrict__ W1,
                                const float* __restrict__ W2) {
    int i = blockIdx.x * blockDim.x + threadIdx.x;
    if (i < 256 * 192) {
        unsigned short hi, lo;
        split_bf(W1[i], hi, lo);
        gW1h[i] = hi; gW1l[i] = lo;
    } else {
        int j = i - 256 * 192;
        if (j < 192 * 128) {
            unsigned short hi, lo;
            split_bf(W2[j], hi, lo);
            gW2h[j] = hi; gW2l[j] = lo;
        }
    }
}

// ================= proj kernel: P = [h@W1_top | h@W1_mid] =================
// (byte-identical to the 684us build)
#define PJ_AH 0
#define PJ_AL 34816
#define PJ_BH 69632
#define PJ_BL 120832
#define PJ_SMEM 172032

__global__ void __launch_bounds__(256, 1)
proj_kernel(const float* __restrict__ h) {
    extern __shared__ __align__(16) unsigned char smem[];
    unsigned short* s_ah = (unsigned short*)(smem + PJ_AH);
    unsigned short* s_al = (unsigned short*)(smem + PJ_AL);
    const int tid = threadIdx.x, w = tid >> 5;
    const int m0 = blockIdx.x * 128;

    {
        const int r = tid >> 1, hk = tid & 1;
        const int m = m0 + r;
        const bool valid = m < N_NODES;
        const float4* hrow = (const float4*)(h + (size_t)m * 128) + hk * 16;
        unsigned* ah = (unsigned*)(s_ah + r * 136 + hk * 64);
        unsigned* al = (unsigned*)(s_al + r * 136 + hk * 64);
#pragma unroll
        for (int i = 0; i < 16; ++i) {
            float4 v = valid ? hrow[i] : make_float4(0.f, 0.f, 0.f, 0.f);
            unsigned short h0, l0, h1, l1, h2, l2, h3, l3;
            split_bf(v.x, h0, l0); split_bf(v.y, h1, l1);
            split_bf(v.z, h2, l2); split_bf(v.w, h3, l3);
            ah[i * 2] = pack2(h0, h1); ah[i * 2 + 1] = pack2(h2, h3);
            al[i * 2] = pack2(l0, l1); al[i * 2 + 1] = pack2(l2, l3);
        }
    }

    const bool strip_ok = (m0 + 16 * w + 16) <= N_NODES;

    for (int half = 0; half < 2; ++half) {
        __syncthreads();
        {
            const uint4* sH = (const uint4*)(gW1h + half * 128 * 192);
            const uint4* sL = (const uint4*)(gW1l + half * 128 * 192);
            uint4* dH = (uint4*)(smem + PJ_BH);
            uint4* dL = (uint4*)(smem + PJ_BL);
            for (int idx = tid; idx < 3072; idx += 256) {
                int row = idx / 24, c = idx - row * 24;
                dH[row * 25 + c] = sH[idx];
                dL[row * 25 + c] = sL[idx];
            }
        }
        __syncthreads();

        if (strip_ok) {
            wmma::fragment<wmma::accumulator, 16, 16, 16, float> acc[12];
#pragma unroll
            for (int n = 0; n < 12; ++n) wmma::fill_fragment(acc[n], 0.f);

#pragma unroll
            for (int k = 0; k < 8; ++k) {
                wmma::fragment<wmma::matrix_a, 16, 16, 16, __nv_bfloat16,
                               wmma::row_major> aH, aL;
                wmma::load_matrix_sync(aH,
                    (const __nv_bfloat16*)(s_ah + (16 * w) * 136 + k * 16), 136);
                wmma::load_matrix_sync(aL,
                    (const __nv_bfloat16*)(s_al + (16 * w) * 136 + k * 16), 136);
#pragma unroll
                for (int n = 0; n < 12; ++n) {
                    wmma::fragment<wmma::matrix_b, 16, 16, 16, __nv_bfloat16,
                                   wmma::row_major> bH, bL;
                    wmma::load_matrix_sync(bH,
                        (const __nv_bfloat16*)(smem + PJ_BH) + (k * 16) * 200 + n * 16, 200);
                    wmma::load_matrix_sync(bL,
                        (const __nv_bfloat16*)(smem + PJ_BL) + (k * 16) * 200 + n * 16, 200);
                    wmma::mma_sync(acc[n], aH, bH, acc[n]);
                    wmma::mma_sync(acc[n], aL, bH, acc[n]);
                    wmma::mma_sync(acc[n], aH, bL, acc[n]);
                }
            }
#pragma unroll
            for (int n = 0; n < 12; ++n)
                wmma::store_matrix_sync(
                    gP + (size_t)(m0 + 16 * w) * 384 + half * 192 + n * 16,
                    acc[n], 384, wmma::mem_row_major);
        }
    }
}

// ================= persistent merged edge kernel =================
// smem: BH 0..52224 (192x136x2B), BL ..104448,
//       A image (single buffer): hi 64x200x2B=25600 @104448, lo @130048,
//       bias [16][128] f32 @155648 (8192), b1 @163840 (768), w1l @164608 (768)
#define EK_BH   0
#define EK_BL   52224
#define EK_A    104448
#define EK_ALO  25600
#define EK_BIAS 155648
#define EK_B1   163840
#define EK_W1L  164608
#define EK_SMEM 165376

__global__ void __launch_bounds__(256, 1)
edge_kernel(const float* __restrict__ dR,
            const int* __restrict__ src_idx, const int* __restrict__ dst_idx,
            const float* __restrict__ W1, const float* __restrict__ b1,
            const float* __restrict__ b2, float* __restrict__ out) {
    extern __shared__ __align__(16) unsigned char smem[];
    float* s_bias = (float*)(smem + EK_BIAS);
    float* s_b1   = (float*)(smem + EK_B1);
    float* s_w1l  = (float*)(smem + EK_W1L);

    const int tid = threadIdx.x, wid = tid >> 5, lane = tid & 31;

    // ---- one-time staging ----
    if (tid < 192) { s_b1[tid] = b1[tid]; s_w1l[tid] = W1[256 * 192 + tid]; }
    for (int idx = tid; idx < 16 * 128; idx += 256) s_bias[idx] = b2[idx & 127];
    {
        const uint4* sH = (const uint4*)gW2h;
        const uint4* sL = (const uint4*)gW2l;
        uint4* dH = (uint4*)(smem + EK_BH);
        uint4* dL = (uint4*)(smem + EK_BL);
        for (int idx = tid; idx < 3072; idx += 256) {
            int row = idx >> 4, c = idx & 15;
            dH[row * 17 + c] = sH[idx];
            dL[row * 17 + c] = sL[idx];
        }
    }
    __syncthreads();

    // gather mapping: 8-lane groups; group g owns edge wid*8 + sr*4 + g
    const int g  = lane >> 3;
    const int l8 = lane & 7;
    const int eb = wid * 8;

    // MMA mapping: 4m x 2n
    const int m0 = (wid & 3) * 16;
    const int n0 = (wid >> 2) * 64;

    unsigned short* s_ah = (unsigned short*)(smem + EK_A);
    unsigned short* s_al = (unsigned short*)(smem + EK_A + EK_ALO);

    int t = blockIdx.x;

    // ---- prime: indices + gather for tile t, indices for t+GRID_P ----
    int ndc[2], nsc[2]; float drc[2];          // current tile (t)
    int ndn[2], nsn[2]; float drn[2];          // next tile (t+GRID_P)
    float4 Ar[2][6], Br[2][6];                 // reg-resident gather

#pragma unroll
    for (int sr = 0; sr < 2; ++sr) {
        const int e = t * 64 + eb + sr * 4 + g;
        ndc[sr] = dst_idx[e]; nsc[sr] = src_idx[e]; drc[sr] = dR[e];
    }
#pragma unroll
    for (int sr = 0; sr < 2; ++sr) {
        const float4* pd = (const float4*)(gP + (size_t)ndc[sr] * 384);
        const float4* ps = (const float4*)(gP + (size_t)nsc[sr] * 384 + 192);
#pragma unroll
        for (int c = 0; c < 6; ++c) Ar[sr][c] = pd[l8 + 8 * c];
#pragma unroll
        for (int c = 0; c < 6; ++c) Br[sr][c] = ps[l8 + 8 * c];
    }
    {
        const int t2 = t + GRID_P;
        const int tc = (t2 < NTILES) ? t2 : t;
#pragma unroll
        for (int sr = 0; sr < 2; ++sr) {
            const int e = tc * 64 + eb + sr * 4 + g;
            ndn[sr] = dst_idx[e]; nsn[sr] = src_idx[e]; drn[sr] = dR[e];
        }
    }

    for (; t < NTILES; t += GRID_P) {
        __syncthreads();   // previous MMA done reading A image

        // ---- convert regs -> smem A image (fuse dR/bias/relu, split hi/lo) ----
#pragma unroll
        for (int sr = 0; sr < 2; ++sr) {
            const int er = eb + sr * 4 + g;
            unsigned* ah = (unsigned*)((unsigned char*)s_ah + er * 400);
            unsigned* al = (unsigned*)((unsigned char*)s_al + er * 400);
            const float drv = drc[sr];
#pragma unroll
            for (int c = 0; c < 6; ++c) {
                const int n = (l8 + 8 * c) * 4;
                float4 w4 = *(const float4*)(s_w1l + n);
                float4 b4 = *(const float4*)(s_b1 + n);
                float v0 = fmaxf(Ar[sr][c].x + Br[sr][c].x + fmaf(drv, w4.x, b4.x), 0.f);
                float v1 = fmaxf(Ar[sr][c].y + Br[sr][c].y + fmaf(drv, w4.y, b4.y), 0.f);
                float v2 = fmaxf(Ar[sr][c].z + Br[sr][c].z + fmaf(drv, w4.z, b4.z), 0.f);
                float v3 = fmaxf(Ar[sr][c].w + Br[sr][c].w + fmaf(drv, w4.w, b4.w), 0.f);
                unsigned hp0 = cvt_bf16x2(v1, v0);
                unsigned hp1 = cvt_bf16x2(v3, v2);
                unsigned lp0 = cvt_bf16x2(v1 - bf_hi_f32(hp0), v0 - bf_lo_f32(hp0));
                unsigned lp1 = cvt_bf16x2(v3 - bf_hi_f32(hp1), v2 - bf_lo_f32(hp1));
                *(uint2*)(ah + (l8 + 8 * c) * 2) = make_uint2(hp0, hp1);
                *(uint2*)(al + (l8 + 8 * c) * 2) = make_uint2(lp0, lp1);
            }
        }
        __syncthreads();   // A image ready

        // ---- issue next tile's gather (hides behind MMA below) ----
        const int t2 = t + GRID_P;
        if (t2 < NTILES) {
#pragma unroll
            for (int sr = 0; sr < 2; ++sr) { ndc[sr] = ndn[sr]; nsc[sr] = nsn[sr]; drc[sr] = drn[sr]; }
#pragma unroll
            for (int sr = 0; sr < 2; ++sr) {
                const float4* pd = (const float4*)(gP + (size_t)ndc[sr] * 384);
                const float4* ps = (const float4*)(gP + (size_t)nsc[sr] * 384 + 192);
#pragma unroll
                for (int c = 0; c < 6; ++c) Ar[sr][c] = pd[l8 + 8 * c];
#pragma unroll
                for (int c = 0; c < 6; ++c) Br[sr][c] = ps[l8 + 8 * c];
            }
            const int t3 = t2 + GRID_P;
            const int tc = (t3 < NTILES) ? t3 : t2;
#pragma unroll
            for (int sr = 0; sr < 2; ++sr) {
                const int e = tc * 64 + eb + sr * 4 + g;
                ndn[sr] = dst_idx[e]; nsn[sr] = src_idx[e]; drn[sr] = dR[e];
            }
        }

        // ---- MMA: 16 rows (m0) x 64 cols (n0), K=192 ----
        wmma::fragment<wmma::accumulator, 16, 16, 16, float> acc[4];
#pragma unroll
        for (int ni = 0; ni < 4; ++ni)
            wmma::load_matrix_sync(acc[ni], s_bias + n0 + ni * 16, 128,
                                   wmma::mem_row_major);

#pragma unroll
        for (int k = 0; k < 12; ++k) {
            wmma::fragment<wmma::matrix_a, 16, 16, 16, __nv_bfloat16,
                           wmma::row_major> aH, aL;
            wmma::load_matrix_sync(aH,
                (const __nv_bfloat16*)(s_ah + m0 * 200 + k * 16), 200);
            wmma::load_matrix_sync(aL,
                (const __nv_bfloat16*)(s_al + m0 * 200 + k * 16), 200);
#pragma unroll
            for (int ni = 0; ni < 4; ++ni) {
                wmma::fragment<wmma::matrix_b, 16, 16, 16, __nv_bfloat16,
                               wmma::row_major> bH, bL;
                wmma::load_matrix_sync(bH,
                    (const __nv_bfloat16*)(smem + EK_BH) + (k * 16) * 136 + n0 + ni * 16, 136);
                wmma::load_matrix_sync(bL,
                    (const __nv_bfloat16*)(smem + EK_BL) + (k * 16) * 136 + n0 + ni * 16, 136);
                wmma::mma_sync(acc[ni], aH, bH, acc[ni]);
                wmma::mma_sync(acc[ni], aL, bH, acc[ni]);
                wmma::mma_sync(acc[ni], aH, bL, acc[ni]);
            }
        }

        // ---- epilogue: tanh + store ----
        const int e0 = t * 64;
#pragma unroll
        for (int ni = 0; ni < 4; ++ni) {
#pragma unroll
            for (int x = 0; x < acc[ni].num_elements; ++x)
                acc[ni].x[x] = fast_tanh(acc[ni].x[x]);
            wmma::store_matrix_sync(out + (size_t)(e0 + m0) * 128 + n0 + ni * 16,
                                    acc[ni], 128, wmma::mem_row_major);
        }
    }
}

extern "C" void kernel_launch(void* const* d_in, const int* in_sizes, int n_in,
                              void* d_out, int out_size) {
    const float* h   = (const float*)d_in[0];
    const float* dR  = (const float*)d_in[1];
    const int*   src = (const int*)  d_in[2];
    const int*   dst = (const int*)  d_in[3];
    const float* W1  = (const float*)d_in[4];
    const float* b1  = (const float*)d_in[5];
    const float* W2  = (const float*)d_in[6];
    const float* b2  = (const float*)d_in[7];
    float* out = (float*)d_out;

    convert_weights<<<288, 256>>>(W1, W2);

    cudaFuncSetAttribute(proj_kernel,
                         cudaFuncAttributeMaxDynamicSharedMemorySize, PJ_SMEM);
    cudaFuncSetAttribute(edge_kernel,
                         cudaFuncAttributeMaxDynamicSharedMemorySize, EK_SMEM);

    proj_kernel<<<(N_NODES + 127) / 128, 256, PJ_SMEM>>>(h);
    edge_kernel<<<GRID_P, 256, EK_SMEM>>>(dR, src, dst, W1, b1, b2, out);
}